// round 14
// baseline (speedup 1.0000x reference)
#include <cuda_runtime.h>
#include <cuda_bf16.h>
#include <cstdint>
#include <math.h>

// ---------------------------------------------------------------------------
// AdvancedAutoInformer — persistent megakernel (v13).
// GEMM via mma.sync.m16n8k16 bf16 with hi/lo split (D += Ah*Bh+Ah*Bl+Al*Bh).
// v13: (1) all weights pre-converted ONCE to bf16 hi/lo in global scratch
// (B-tiles become plain bf16 copies), (2) fragment loads via ldmatrix.x4
// (8 LDSM vs 32 LDS.32 per warp-k16). Everything else identical to v12.
// Domain reduction: only token 3999 matters; block-local attention (BLOCK=20)
// => tokens [3980,4000). B=32, S=20, D=256, H=8, F=1024, L=4.
// One kernel, 148 CTAs x 512 threads, device-wide counter barriers.
// ---------------------------------------------------------------------------

#define NCTA  148
#define NTHR  512
#define NTOK  640
#define N1    (NTOK*256)
#define POOLB 75776

// smem byte offsets: 4 bf16 tiles of 128 rows x 72 (stride 144 B) = 18432 B
#define SM_AH 1024u
#define SM_AL 19456u
#define SM_BH 37888u
#define SM_BL 56320u

// pre-converted weight buffer offsets (elements)
#define WOFF_C2 0L
#define WOFF_TS 196608L
#define WOFF_LYR(i) (327680L + (long)(i)*786432L)
#define WTOTAL 3473408L

// Scratch (static device arrays; zero runtime allocation).
__device__ __align__(16) float g_c1col[NTOK*768];
__device__ __align__(16) float g_hf  [N1];
__device__ __align__(16) float g_h   [N1];
__device__ __align__(16) float g_qkvp[24*N1];   // QKV (4x3N1) / FF2 (8xN1) partials
__device__ __align__(16) float g_att [N1];
__device__ __align__(16) float g_part[24*N1];   // generic split-K partial chunks
__device__ __align__(16) __nv_bfloat16 g_wh[WTOTAL];
__device__ __align__(16) __nv_bfloat16 g_wl[WTOTAL];
__device__ unsigned g_bars[64];
__device__ unsigned g_done;

// ---------------- device-wide barrier (148 co-resident CTAs) ----------------
__device__ __forceinline__ void gsync(int id){
  __syncthreads();
  if (threadIdx.x == 0){
    __threadfence();
    atomicAdd(&g_bars[id], 1u);
    volatile unsigned* p = &g_bars[id];
    while (*p < NCTA) { }
    __threadfence();
  }
  __syncthreads();
}

// ---------------- bf16 mma.sync / ldmatrix ----------------
__device__ __forceinline__ void mma_bf16(float* c, const uint32_t* a,
                                         const uint32_t* b){
  asm volatile(
    "mma.sync.aligned.m16n8k16.row.col.f32.bf16.bf16.f32 "
    "{%0,%1,%2,%3},{%4,%5,%6,%7},{%8,%9},{%0,%1,%2,%3};"
    : "+f"(c[0]), "+f"(c[1]), "+f"(c[2]), "+f"(c[3])
    : "r"(a[0]), "r"(a[1]), "r"(a[2]), "r"(a[3]), "r"(b[0]), "r"(b[1]));
}
#define LDSM_X4(r, addr) \
  asm volatile("ldmatrix.sync.aligned.m8n8.x4.shared.b16 {%0,%1,%2,%3}, [%4];" \
    : "=r"((r)[0]), "=r"((r)[1]), "=r"((r)[2]), "=r"((r)[3]) : "r"(addr))

// pack hi/lo bf16x2 words of (v0, v1): hi = round(v), lo = round(v - hi)
__device__ __forceinline__ void split_pack(float v0, float v1,
                                           uint32_t& hw, uint32_t& lw){
  __nv_bfloat162 hp = __floats2bfloat162_rn(v0, v1);
  __nv_bfloat162 lp = __floats2bfloat162_rn(v0 - __bfloat162float(hp.x),
                                            v1 - __bfloat162float(hp.y));
  hw = *(uint32_t*)&hp;
  lw = *(uint32_t*)&lp;
}

// startup: elementwise weight split fp32 -> (g_wh, g_wl)
__device__ void wconv(const float* __restrict__ src, long off, int count){
  int stride = NCTA*NTHR;
  for (int i = blockIdx.x*NTHR + threadIdx.x; i < count; i += stride){
    float v = src[i];
    __nv_bfloat16 h = __float2bfloat16(v);
    g_wh[off + i] = h;
    g_wl[off + i] = __float2bfloat16(v - __bfloat162float(h));
  }
}

// ---------------------------------------------------------------------------
// Tensor GEMM phase: C[m][n] = sum_k Aeff[m][k0+k] * W[n][k0+k]  (NT)
// Aeff = A (a2count==1) or relu(sum_c A[c*a2stride+..] + abias[k]) (FF1->FF2).
// W read from pre-converted g_wh/g_wl at element offset woff, row stride ldw.
// Job = 128x128 tile, z-th K-range of klen (slabs of 64). 16 warps 4x4,
// warp tile 32x32 = 2x4 m16n8 fragments. Raw fp32 partials to C + z*640*N.
// ---------------------------------------------------------------------------
__device__ void gemm_mma(char* sm, uint32_t smb,
    const float* __restrict__ A, int a2count, long a2stride,
    const float* __restrict__ abias, int lda,
    long woff, int ldw,
    float* C, int N, int splitk, int klen)
{
  const int tiles_n = N >> 7;
  const int njobs = 5 * tiles_n * splitk;
  const int tid = threadIdx.x;
  const int wid = tid >> 5, lane = tid & 31;
  const int wm = wid >> 2, wn = wid & 3;
  const int lr = lane >> 2, lc = lane & 3;

  uint32_t* AH = (uint32_t*)(sm + SM_AH);
  uint32_t* AL = (uint32_t*)(sm + SM_AL);
  uint32_t* BH = (uint32_t*)(sm + SM_BH);
  uint32_t* BL = (uint32_t*)(sm + SM_BL);

  // conversion/copy mapping: row = tid>>2, 16 k-elements starting at kb
  const int crow = tid >> 2;
  const int kb   = (tid & 3) << 4;
  const int kb2  = kb >> 1;               // word offset

  // ldmatrix lane base addresses (constant per phase; +s4*32 bytes per k16)
  const int l15 = lane & 15, lh = lane >> 4;
  const uint32_t aoff = (uint32_t)((wm*32 + l15)*144 + lh*16);
  const uint32_t aAH0 = smb + SM_AH + aoff;
  const uint32_t aAL0 = smb + SM_AL + aoff;
  const int bg = lane >> 3, br = lane & 7;
  const uint32_t boff = (uint32_t)((wn*32 + (bg & 1)*8 + br)*144 + (bg >> 1)*16);
  const uint32_t bBH0 = smb + SM_BH + boff;
  const uint32_t bBL0 = smb + SM_BL + boff;

  for (int job = blockIdx.x; job < njobs; job += NCTA){
    int z    = job / (5*tiles_n);
    int rest = job - z*(5*tiles_n);
    int tm_  = rest / tiles_n;
    int tn_  = rest - tm_*tiles_n;
    int m0 = tm_*128, n0 = tn_*128, k0 = z*klen;

    float acc[32];
    #pragma unroll
    for (int q = 0; q < 32; q++) acc[q] = 0.f;

    const int nslab = klen >> 6;
    for (int s = 0; s < nslab; s++){
      int ks = k0 + s*64;

      // ---- convert A tile (128 x 64 fp32 -> hi/lo)
      {
        const float* src = A + (long)(m0 + crow)*lda + ks + kb;
        float v[16];
        #pragma unroll
        for (int q = 0; q < 16; q += 4){
          float4 t = *(const float4*)(src + q);
          v[q] = t.x; v[q+1] = t.y; v[q+2] = t.z; v[q+3] = t.w;
        }
        if (a2count > 1){
          for (int c = 1; c < a2count; c++){
            const float* s2 = src + (long)c*a2stride;
            #pragma unroll
            for (int q = 0; q < 16; q += 4){
              float4 t = *(const float4*)(s2 + q);
              v[q] += t.x; v[q+1] += t.y; v[q+2] += t.z; v[q+3] += t.w;
            }
          }
          const float* bb = abias + ks + kb;
          #pragma unroll
          for (int q = 0; q < 16; q++) v[q] = fmaxf(v[q] + bb[q], 0.f);
        }
        uint32_t hw[8], lw[8];
        #pragma unroll
        for (int q = 0; q < 8; q++) split_pack(v[2*q], v[2*q+1], hw[q], lw[q]);
        int base = crow*36 + kb2;
        *(uint4*)(AH + base)     = make_uint4(hw[0],hw[1],hw[2],hw[3]);
        *(uint4*)(AH + base + 4) = make_uint4(hw[4],hw[5],hw[6],hw[7]);
        *(uint4*)(AL + base)     = make_uint4(lw[0],lw[1],lw[2],lw[3]);
        *(uint4*)(AL + base + 4) = make_uint4(lw[4],lw[5],lw[6],lw[7]);
      }
      // ---- copy B tile (pre-converted bf16 hi/lo, 128 rows x 64)
      {
        long wsrc = woff + (long)(n0 + crow)*ldw + ks + kb;
        uint4 h0 = *(const uint4*)(g_wh + wsrc);
        uint4 h1 = *(const uint4*)(g_wh + wsrc + 8);
        uint4 l0 = *(const uint4*)(g_wl + wsrc);
        uint4 l1 = *(const uint4*)(g_wl + wsrc + 8);
        int base = crow*36 + kb2;
        *(uint4*)(BH + base)     = h0;
        *(uint4*)(BH + base + 4) = h1;
        *(uint4*)(BL + base)     = l0;
        *(uint4*)(BL + base + 4) = l1;
      }
      __syncthreads();

      // ---- 4 k16-steps: ldmatrix fragments + mma
      #pragma unroll
      for (int s4 = 0; s4 < 4; s4++){
        const uint32_t kofs = s4*32;
        uint32_t ah[2][4], al[2][4], bh[4][2], bl[4][2];
        #pragma unroll
        for (int t = 0; t < 2; t++){
          LDSM_X4(ah[t], aAH0 + t*2304 + kofs);
          LDSM_X4(al[t], aAL0 + t*2304 + kofs);
        }
        #pragma unroll
        for (int p = 0; p < 2; p++){
          uint32_t r[4];
          LDSM_X4(r, bBH0 + p*2304 + kofs);
          bh[2*p][0] = r[0]; bh[2*p][1] = r[2];
          bh[2*p+1][0] = r[1]; bh[2*p+1][1] = r[3];
          LDSM_X4(r, bBL0 + p*2304 + kofs);
          bl[2*p][0] = r[0]; bl[2*p][1] = r[2];
          bl[2*p+1][0] = r[1]; bl[2*p+1][1] = r[3];
        }
        #pragma unroll
        for (int tm = 0; tm < 2; tm++)
          #pragma unroll
          for (int tn = 0; tn < 4; tn++){
            float* c = &acc[(tm*4 + tn)*4];
            mma_bf16(c, ah[tm], bh[tn]);
            mma_bf16(c, ah[tm], bl[tn]);
            mma_bf16(c, al[tm], bh[tn]);
          }
      }
      __syncthreads();
    }

    // ---- epilogue: raw fp32 partial store
    float* Cz = C + (long)z*640*N;
    #pragma unroll
    for (int tm = 0; tm < 2; tm++)
      #pragma unroll
      for (int tn = 0; tn < 4; tn++){
        const float* c = &acc[(tm*4 + tn)*4];
        int row = m0 + wm*32 + tm*16 + lr;
        int col = n0 + wn*32 + tn*8 + 2*lc;
        *(float2*)&Cz[(long)row*N + col]       = make_float2(c[0], c[1]);
        *(float2*)&Cz[(long)(row + 8)*N + col] = make_float2(c[2], c[3]);
      }
  }
}

// ---------------------------------------------------------------------------
// conv1 (C=16 -> D=256, k=3, SAME) + relu -> im2col layout in g_c1col.
// ---------------------------------------------------------------------------
__device__ void conv1_dev(float* pool, const float* __restrict__ x,
                          const float* __restrict__ w,
                          const float* __restrict__ bias){
  if (blockIdx.x < 32){
    float* xs = pool;                       // 23*16 floats
    int b = blockIdx.x, tid = threadIdx.x;
    for (int idx = tid; idx < 23*16; idx += NTHR){
      int j = idx >> 4, c = idx & 15;
      int t = 3978 + j;
      xs[idx] = (t < 4000) ? x[(b*4000 + t)*16 + c] : 0.f;
    }
    __syncthreads();
    if (tid < 256){
      int d = tid;
      float wr[48];
      #pragma unroll
      for (int q = 0; q < 48; q++) wr[q] = w[d*48 + q];
      float bb = bias[d];
      for (int p = 0; p < 22; p++){
        float val = 0.f;
        if (p < 21){
          float acc = bb;
          #pragma unroll
          for (int k = 0; k < 3; k++)
            #pragma unroll
            for (int c = 0; c < 16; c++)
              acc += wr[c*3 + k] * xs[(p + k)*16 + c];
          val = fmaxf(acc, 0.f);
        }
        #pragma unroll
        for (int k = 0; k < 3; k++){
          int i = p - k;
          if (i >= 0 && i < 20)
            g_c1col[(b*20 + i)*768 + d*3 + k] = val;
        }
      }
    }
    __syncthreads();
  }
}

// ---------------------------------------------------------------------------
// Warp-per-row LayerNorm family. Rows spread across ALL 148 CTAs.
// ---------------------------------------------------------------------------
__device__ __forceinline__ float wsum(float v){
  #pragma unroll
  for (int o = 16; o > 0; o >>= 1) v += __shfl_xor_sync(0xffffffffu, v, o);
  return v;
}

__device__ void ln_rows(const float* __restrict__ res,
                        const float* __restrict__ part, int nch, long chs,
                        const float* __restrict__ bias,
                        const float* __restrict__ g,
                        const float* __restrict__ bta,
                        float* __restrict__ out, int relu){
  int row = (threadIdx.x >> 5)*NCTA + blockIdx.x;
  if (row >= NTOK) return;
  int lane = threadIdx.x & 31;
  int base = row*256;
  float v[8];
  float s = 0.f;
  #pragma unroll
  for (int q = 0; q < 8; q++){
    int d = q*32 + lane;
    float t = bias[d];
    for (int c = 0; c < nch; c++) t += part[(long)c*chs + base + d];
    if (res) t += res[base + d];
    if (relu) t = fmaxf(t, 0.f);
    v[q] = t; s += t;
  }
  float mean = wsum(s) * (1.f/256.f);
  float s2 = 0.f;
  #pragma unroll
  for (int q = 0; q < 8; q++){ float c = v[q]-mean; s2 += c*c; }
  float inv = rsqrtf(wsum(s2) * (1.f/256.f) + 1e-5f);
  #pragma unroll
  for (int q = 0; q < 8; q++){
    int d = q*32 + lane;
    out[base + d] = (v[q]-mean)*inv*g[d] + bta[d];
  }
}

// h = hf + (trend + tb) + sin(season + sb); dual partials: 4 chunks of 640x512.
__device__ void hcomb_dev(const float* __restrict__ tb,
                          const float* __restrict__ sb){
  int row = (threadIdx.x >> 5)*NCTA + blockIdx.x;
  if (row >= NTOK) return;
  int lane = threadIdx.x & 31;
  #pragma unroll
  for (int q = 0; q < 8; q++){
    int d = q*32 + lane;
    long o = (long)row*512 + d;
    float tr = tb[d], se = sb[d];
    #pragma unroll
    for (int z = 0; z < 4; z++){
      tr += g_part[(long)z*2*N1 + o];
      se += g_part[(long)z*2*N1 + o + 256];
    }
    g_h[row*256 + d] = g_hf[row*256 + d] + tr + sinf(se);
  }
}

// ---------------------------------------------------------------------------
// Attention: 128 CTAs, one per (batch, head-pair). Fuses the QKV 4-chunk
// split-K reduce + bias. Warp-per-(head,token) compute (lane = dim).
// ---------------------------------------------------------------------------
__device__ void attn_dev(float* pool, const float* __restrict__ bias){
  if (blockIdx.x >= 128) return;
  int b = blockIdx.x >> 2, hp = blockIdx.x & 3;      // heads 2hp, 2hp+1
  int tid = threadIdx.x;
  float* sk = pool;             // [2][20][32]
  float* sv = pool + 1280;      // [2][20][32]
  const long CH = (long)NTOK*768;
  for (int e = tid; e < 1280; e += NTHR){
    int hl = e / 640, rem = e - hl*640;
    int j = rem >> 5, t = rem & 31;
    int h = 2*hp + hl;
    long o = (long)(b*20 + j)*768 + 256 + h*32 + t;
    float kk = bias[256 + h*32 + t], vv = bias[512 + h*32 + t];
    #pragma unroll
    for (int c = 0; c < 4; c++){
      kk += g_qkvp[c*CH + o];
      vv += g_qkvp[c*CH + o + 256];
    }
    sk[e] = kk; sv[e] = vv;
  }
  __syncthreads();

  int w = tid >> 5, lane = tid & 31;
  for (int task = w; task < 40; task += 16){
    int hl = task / 20, i = task - hl*20;
    int h = 2*hp + hl;
    long qo = (long)(b*20 + i)*768 + h*32 + lane;
    float q = bias[h*32 + lane];
    #pragma unroll
    for (int c = 0; c < 4; c++) q += g_qkvp[c*CH + qo];
    float sc[20];
    float mx = -1e30f;
    #pragma unroll
    for (int j = 0; j < 20; j++){
      float p = q * sk[(hl*20 + j)*32 + lane];
      p = wsum(p) * 0.17677669529663687f;            // 1/sqrt(32)
      sc[j] = p;
      mx = fmaxf(mx, p);
    }
    float ssum = 0.f;
    #pragma unroll
    for (int j = 0; j < 20; j++){ sc[j] = expf(sc[j] - mx); ssum += sc[j]; }
    float inv = 1.f / ssum;
    float o = 0.f;
    #pragma unroll
    for (int j = 0; j < 20; j++) o += sc[j] * sv[(hl*20 + j)*32 + lane];
    g_att[(b*20 + i)*256 + h*32 + lane] = o * inv;
  }
}

// ---------------------------------------------------------------------------
// Final: out[b*16+c] = h[b,last,:] . fc_w[c,:] + fc_b[c]
// ---------------------------------------------------------------------------
__device__ void final_dev(const float* __restrict__ fw,
                          const float* __restrict__ fb,
                          float* __restrict__ out){
  int gw = (threadIdx.x >> 5)*NCTA + blockIdx.x;
  if (gw >= 512) return;
  int lane = threadIdx.x & 31;
  int b = gw >> 4, c = gw & 15;
  const float* hr = g_h + (b*20 + 19)*256;
  const float* wr = fw + c*256;
  float s = 0.f;
  #pragma unroll
  for (int q = 0; q < 8; q++){
    int d = q*32 + lane;
    s += hr[d]*wr[d];
  }
  s = wsum(s);
  if (lane == 0) out[gw] = s + fb[c];
}

// ---------------------------------------------------------------------------
__global__ void __launch_bounds__(NTHR, 1)
mega_kernel(const float* x,
            const float* c1w, const float* c1b,
            const float* c2w, const float* c2b,
            const float* lnfg, const float* lnfb,
            const float* tw, const float* tb,
            const float* sw, const float* sb,
            const float* aiw, const float* aib,
            const float* aow, const float* aob,
            const float* l1g, const float* l1b,
            const float* f1w, const float* f1b,
            const float* f2w, const float* f2b,
            const float* l2g, const float* l2b,
            const float* fcw, const float* fcb,
            float* out)
{
  extern __shared__ __align__(16) char smpool[];
  float* pool = (float*)smpool;
  uint32_t smb;
  asm("{ .reg .u64 t; cvta.to.shared.u64 t, %1; cvt.u32.u64 %0, t; }"
      : "=r"(smb) : "l"(smpool));
  int bar = 0;

  // startup: weight pre-conversion (grid-strided) + conv1, one barrier
  wconv(c2w, WOFF_C2, 196608);
  wconv(tw,  WOFF_TS, 65536);
  wconv(sw,  WOFF_TS + 65536, 65536);
  for (int i = 0; i < 4; i++){
    wconv(aiw + (long)i*196608, WOFF_LYR(i),          196608);
    wconv(aow + (long)i*65536,  WOFF_LYR(i) + 196608, 65536);
    wconv(f1w + (long)i*262144, WOFF_LYR(i) + 262144, 262144);
    wconv(f2w + (long)i*262144, WOFF_LYR(i) + 524288, 262144);
  }
  conv1_dev(pool, x, c1w, c1b);
  gsync(bar++);

  // conv2: K=768, splitK 12 (klen 64) -> 12 chunks of N1, 120 jobs
  gemm_mma(smpool, smb, g_c1col, 1, 0, nullptr, 768,
           WOFF_C2, 768, g_part, 256, 12, 64);
  gsync(bar++);
  ln_rows(nullptr, g_part, 12, N1, c2b, lnfg, lnfb, g_hf, 1);
  gsync(bar++);
  // trend|season concat: N=512, K=256, splitK 4 (klen 64) -> 4 dual chunks
  gemm_mma(smpool, smb, g_hf, 1, 0, nullptr, 256,
           WOFF_TS, 256, g_part, 512, 4, 64);
  gsync(bar++);
  hcomb_dev(tb, sb);
  gsync(bar++);

  for (int i = 0; i < 4; i++){
    // QKV: N=768, K=256, splitK 4 (klen 64) -> 4 chunks of 3*N1, 120 jobs
    gemm_mma(smpool, smb, g_h, 1, 0, nullptr, 256,
             WOFF_LYR(i), 256, g_qkvp, 768, 4, 64);
    gsync(bar++);
    attn_dev(pool, aib + i*768);
    gsync(bar++);
    // out-proj: N=256, K=256, splitK 4 (klen 64) -> 4 chunks, 40 jobs
    gemm_mma(smpool, smb, g_att, 1, 0, nullptr, 256,
             WOFF_LYR(i) + 196608, 256, g_part, 256, 4, 64);
    gsync(bar++);
    ln_rows(g_h, g_part, 4, N1, aob + i*256, l1g + i*256, l1b + i*256, g_h, 0);
    gsync(bar++);
    // FF1: N=1024, K=256, splitK 2 (klen 128) -> 2 raw chunks of 4*N1, 80 jobs
    gemm_mma(smpool, smb, g_h, 1, 0, nullptr, 256,
             WOFF_LYR(i) + 262144, 256, g_part, 1024, 2, 128);
    gsync(bar++);
    // FF2: N=256, K=1024, splitK 8 (klen 128) -> 8 chunks into g_qkvp, 80 jobs.
    // A = relu(p0 + p1 + ff1_bias) fused into the A-tile conversion.
    gemm_mma(smpool, smb, g_part, 2, (long)4*N1, f1b + i*1024, 1024,
             WOFF_LYR(i) + 524288, 1024, g_qkvp, 256, 8, 128);
    gsync(bar++);
    ln_rows(g_h, g_qkvp, 8, N1, f2b + i*256, l2g + i*256, l2b + i*256,
            g_h, 0);
    gsync(bar++);
  }

  final_dev(fcw, fcb, out);

  // termination + reset for next graph replay
  __syncthreads();
  if (threadIdx.x == 0){
    __threadfence();
    unsigned old = atomicAdd(&g_done, 1u);
    if (old == NCTA - 1){
      #pragma unroll
      for (int i = 0; i < 64; i++) g_bars[i] = 0;
      g_done = 0;
      __threadfence();
    }
  }
}

// ---------------------------------------------------------------------------
extern "C" void kernel_launch(void* const* d_in, const int* in_sizes, int n_in,
                              void* d_out, int out_size){
  (void)in_sizes; (void)n_in; (void)out_size;
  cudaFuncSetAttribute(mega_kernel,
                       cudaFuncAttributeMaxDynamicSharedMemorySize, POOLB);
  mega_kernel<<<NCTA, NTHR, POOLB>>>(
      (const float*)d_in[0],  (const float*)d_in[1],  (const float*)d_in[2],
      (const float*)d_in[3],  (const float*)d_in[4],  (const float*)d_in[5],
      (const float*)d_in[6],  (const float*)d_in[7],  (const float*)d_in[8],
      (const float*)d_in[9],  (const float*)d_in[10], (const float*)d_in[11],
      (const float*)d_in[12], (const float*)d_in[13], (const float*)d_in[14],
      (const float*)d_in[15], (const float*)d_in[16], (const float*)d_in[17],
      (const float*)d_in[18], (const float*)d_in[19], (const float*)d_in[20],
      (const float*)d_in[21], (const float*)d_in[22], (const float*)d_in[23],
      (const float*)d_in[24], (float*)d_out);
}